// round 5
// baseline (speedup 1.0000x reference)
#include <cuda_runtime.h>
#include <math.h>

#define BS 16
#define NQ 1024   // columns m (queries)
#define NT 128    // rows n (targets)
#define INF_F 1e9f
#define FULL 0xffffffffu

// 16 * 128 * 1024 * 4B = 8 MB cost scratch
__device__ float g_cost[BS * NT * NQ];

// ---------------------------------------------------------------------------
// Kernel 1: cost matrix C[b][t][q] = 5*(|dx|+|dy|) + |sigmoid(ql)-tl|
// FMA contraction suppressed so rounding matches mul-then-add.
// ---------------------------------------------------------------------------
__global__ void __launch_bounds__(1024) cost_kernel(
    const float* __restrict__ qc,   // [BS, NQ, 2]
    const float* __restrict__ ql,   // [BS, NQ, 1]
    const float* __restrict__ tc,   // [BS, NT, 2]
    const float* __restrict__ tl)   // [BS, NT, 1]
{
    int b = blockIdx.x;
    int q = threadIdx.x;

    __shared__ float s_tx[NT], s_ty[NT], s_tp[NT];
    if (q < NT) {
        s_tx[q] = tc[(b * NT + q) * 2 + 0];
        s_ty[q] = tc[(b * NT + q) * 2 + 1];
        s_tp[q] = tl[b * NT + q];
    }

    float x = qc[(b * NQ + q) * 2 + 0];
    float y = qc[(b * NQ + q) * 2 + 1];
    float s = 1.0f / (1.0f + expf(-ql[b * NQ + q]));

    __syncthreads();

    float* Cb = g_cost + (size_t)b * NT * NQ;
    for (int t = 0; t < NT; t++) {
        float dsum = __fadd_rn(fabsf(__fadd_rn(x, -s_tx[t])),
                               fabsf(__fadd_rn(y, -s_ty[t])));
        float c = __fadd_rn(__fmul_rn(5.0f, dsum),
                            fabsf(__fadd_rn(s, -s_tp[t])));
        Cb[t * NQ + q] = c;
    }
}

// ---------------------------------------------------------------------------
// Kernel 2: Jonker-Volgenant LSA. ONE WARP per batch. Lane owns columns
// j = 1 + lane + 32*k. 'used' flags in per-lane register bitmasks.
// Faithful transcription (same updates, first-index argmin tie-break).
// Output written as FLOAT (harness __output__ dtype hypothesis).
// ---------------------------------------------------------------------------
__global__ void __launch_bounds__(32) lsa_kernel(float* __restrict__ out)
{
    const int b = blockIdx.x;
    const int lane = threadIdx.x;
    const float* C = g_cost + (size_t)b * NT * NQ;

    __shared__ float v[NQ + 1];
    __shared__ float minv[NQ + 1];
    __shared__ int   way[NQ + 1];
    __shared__ int   p[NQ + 1];
    __shared__ float u[NT + 1];

    for (int k = lane; k <= NQ; k += 32) { v[k] = 0.0f; p[k] = 0; }
    for (int k = lane; k <= NT; k += 32) u[k] = 0.0f;
    __syncwarp();

    for (int i = 1; i <= NT; i++) {
#pragma unroll
        for (int k = 0; k < 32; k++) {
            int j = 1 + lane + 32 * k;
            minv[j] = INF_F;
            way[j]  = 0;
        }
        unsigned umask = 0u;            // used bits for this lane's columns
        if (lane == 0) p[0] = i;
        __syncwarp();

        int j0 = 0;                     // column 0 is used from the start
        while (true) {
            if (j0 != 0 && ((j0 - 1) & 31) == lane)
                umask |= 1u << ((j0 - 1) >> 5);

            const int   i0  = p[j0];    // stable between syncwarps
            const float ui0 = u[i0];
            const float* row = C + (size_t)(i0 - 1) * NQ;

            // relax own columns + local lexicographic min
            float bestv = INF_F;
            int   besti = NQ + 1;
#pragma unroll
            for (int k = 0; k < 32; k++) {
                int j = 1 + lane + 32 * k;
                if (!(umask & (1u << k))) {
                    float cur = row[j - 1] - ui0 - v[j];
                    float m = minv[j];
                    if (cur < m) { m = cur; minv[j] = cur; way[j] = j0; }
                    if (m < bestv || (m == bestv && j < besti)) { bestv = m; besti = j; }
                }
            }

            // warp argmin, lexicographic (val, idx) == first-index argmin
#pragma unroll
            for (int off = 16; off; off >>= 1) {
                float ov = __shfl_xor_sync(FULL, bestv, off);
                int   oi = __shfl_xor_sync(FULL, besti, off);
                if (ov < bestv || (ov == bestv && oi < besti)) { bestv = ov; besti = oi; }
            }
            const float delta = bestv;
            const int   j1    = besti;

            // dual updates (used -> v-=d, u[p]+=d; unused -> minv-=d)
#pragma unroll
            for (int k = 0; k < 32; k++) {
                int j = 1 + lane + 32 * k;
                if (umask & (1u << k)) {
                    v[j] -= delta;
                    u[p[j]] += delta;   // distinct rows across used: race-free
                } else {
                    minv[j] -= delta;
                }
            }
            if (lane == 0) {            // column 0 (always used)
                v[0] -= delta;
                u[p[0]] += delta;
            }
            __syncwarp();               // publish u/v/minv/way

            j0 = j1;
            if (p[j0] == 0) break;      // reached a free column
        }

        // augment along way[] (lane 0 only)
        if (lane == 0) {
            int jj = j0;
            do {
                int jn = way[jj];
                p[jj] = p[jn];
                jj = jn;
            } while (jj != 0);
        }
        __syncwarp();                   // publish p
    }

    // output: rows = ascending matched query ids, cols = their target ids
    if (lane == 0) {
        int k = 0;
        for (int j = 1; j <= NQ; j++) {
            int pi = p[j];
            if (pi > 0) {
                out[b * NT + k]           = (float)(j - 1);   // rows (query)
                out[BS * NT + b * NT + k] = (float)(pi - 1);  // cols (target)
                k++;
            }
        }
    }
}

// ---------------------------------------------------------------------------
extern "C" void kernel_launch(void* const* d_in, const int* in_sizes, int n_in,
                              void* d_out, int out_size)
{
    // Identify inputs by element count (robust to ordering):
    //   corner_coord 16*1024*2=32768, corner_logits 16*1024=16384,
    //   tgt_coords 16*128*2=4096, tgt_labels 16*128=2048.
    const float *qc = 0, *ql = 0, *tc = 0, *tl = 0;
    for (int i = 0; i < n_in; i++) {
        switch (in_sizes[i]) {
            case 32768: qc = (const float*)d_in[i]; break;
            case 16384: ql = (const float*)d_in[i]; break;
            case 4096:  tc = (const float*)d_in[i]; break;
            case 2048:  tl = (const float*)d_in[i]; break;
        }
    }

    cost_kernel<<<BS, 1024>>>(qc, ql, tc, tl);
    lsa_kernel<<<BS, 32>>>((float*)d_out);
}

// round 6
// speedup vs baseline: 3.0776x; 3.0776x over previous
#include <cuda_runtime.h>
#include <math.h>

#define BS 16
#define NQ 1024   // columns m (queries)
#define NT 128    // rows n (targets)
#define INF_F 1e9f
#define FULL 0xffffffffu

// 16 * 128 * 1024 * 4B = 8 MB cost scratch
__device__ __align__(16) float g_cost[BS * NT * NQ];

// ---------------------------------------------------------------------------
// Kernel 1: cost matrix C[b][t][q] = 5*(|dx|+|dy|) + |sigmoid(ql)-tl|
// FMA contraction suppressed so rounding matches mul-then-add.
// ---------------------------------------------------------------------------
__global__ void __launch_bounds__(1024) cost_kernel(
    const float* __restrict__ qc,   // [BS, NQ, 2]
    const float* __restrict__ ql,   // [BS, NQ, 1]
    const float* __restrict__ tc,   // [BS, NT, 2]
    const float* __restrict__ tl)   // [BS, NT, 1]
{
    int b = blockIdx.x;
    int q = threadIdx.x;

    __shared__ float s_tx[NT], s_ty[NT], s_tp[NT];
    if (q < NT) {
        s_tx[q] = tc[(b * NT + q) * 2 + 0];
        s_ty[q] = tc[(b * NT + q) * 2 + 1];
        s_tp[q] = tl[b * NT + q];
    }

    float x = qc[(b * NQ + q) * 2 + 0];
    float y = qc[(b * NQ + q) * 2 + 1];
    float s = 1.0f / (1.0f + expf(-ql[b * NQ + q]));

    __syncthreads();

    float* Cb = g_cost + (size_t)b * NT * NQ;
    for (int t = 0; t < NT; t++) {
        float dsum = __fadd_rn(fabsf(__fadd_rn(x, -s_tx[t])),
                               fabsf(__fadd_rn(y, -s_ty[t])));
        float c = __fadd_rn(__fmul_rn(5.0f, dsum),
                            fabsf(__fadd_rn(s, -s_tp[t])));
        Cb[t * NQ + q] = c;
    }
}

// ---------------------------------------------------------------------------
// Kernel 2: Jonker-Volgenant LSA, one warp per batch. Lane owns the 32
// CONTIGUOUS columns j in [lane*32+1, lane*32+32]. v/minv in registers,
// row reads via float4 + software prefetch, argmin via redux.sync.
// Exact same float op sequence as the reference -> bit-identical result.
// ---------------------------------------------------------------------------
__global__ void __launch_bounds__(32) lsa_kernel(float* __restrict__ out)
{
    const int b = blockIdx.x;
    const int lane = threadIdx.x;
    const float* C = g_cost + (size_t)b * NT * NQ;

    __shared__ float s_u[NT + 1];
    __shared__ int   s_p[NQ + 1];
    __shared__ int   s_way[NQ + 1];

    float v[32];
    float mv[32];

#pragma unroll
    for (int k = 0; k < 32; k++) v[k] = 0.0f;
    for (int j = lane; j <= NQ; j += 32) s_p[j] = 0;
    for (int r = lane; r <= NT; r += 32) s_u[r] = 0.0f;
    __syncwarp();

    const int jbase = lane * 32 + 1;   // first column this lane owns

    for (int i = 1; i <= NT; i++) {
#pragma unroll
        for (int k = 0; k < 32; k++) mv[k] = INF_F;
        unsigned umask = 0u;
        if (lane == 0) s_p[0] = i;

        int   i0  = i;
        float ui0 = s_u[i];          // == 0 for a fresh free row
        float u_acc = ui0;           // lane0: accumulates u[p[0]] adds
        __syncwarp();

        // prefetch first row
        float rowbuf[32];
        {
            const float4* rp = (const float4*)(C + (size_t)(i0 - 1) * NQ + lane * 32);
#pragma unroll
            for (int q4 = 0; q4 < 8; q4++) {
                float4 r4 = rp[q4];
                rowbuf[q4 * 4 + 0] = r4.x; rowbuf[q4 * 4 + 1] = r4.y;
                rowbuf[q4 * 4 + 2] = r4.z; rowbuf[q4 * 4 + 3] = r4.w;
            }
        }

        int j0 = 0;
        int jfree;
        while (true) {
            // ---- relax own columns (registers) ----
#pragma unroll
            for (int k = 0; k < 32; k++) {
                if (!((umask >> k) & 1u)) {
                    float cur = rowbuf[k] - ui0 - v[k];
                    if (cur < mv[k]) { mv[k] = cur; s_way[jbase + k] = j0; }
                }
            }

            // ---- local argmin tree (lower idx wins ties) ----
            float tv[32]; int ti[32];
#pragma unroll
            for (int k = 0; k < 32; k++) {
                tv[k] = ((umask >> k) & 1u) ? INF_F : mv[k];
                ti[k] = jbase + k;
            }
#pragma unroll
            for (int s = 1; s < 32; s <<= 1) {
#pragma unroll
                for (int k = 0; k < 32; k += 2 * s) {
                    if (tv[k + s] < tv[k]) { tv[k] = tv[k + s]; ti[k] = ti[k + s]; }
                }
            }

            // ---- warp argmin via redux (lexicographic: val, then j) ----
            float cv = tv[0] + 0.0f;                 // canonicalize -0 -> +0
            unsigned ub  = __float_as_uint(cv);
            unsigned key = (ub & 0x80000000u) ? ~ub : (ub | 0x80000000u);
            unsigned mk  = __reduce_min_sync(FULL, key);
            unsigned ci  = (key == mk) ? (unsigned)ti[0] : 0xffffffffu;
            int      j1  = (int)__reduce_min_sync(FULL, ci);
            unsigned du  = (mk & 0x80000000u) ? (mk ^ 0x80000000u) : ~mk;
            float delta  = __uint_as_float(du);

            // ---- next-row prep + prefetch (u[i0n] untouched this round) ----
            int  pj1  = s_p[j1];
            bool done = (pj1 == 0);
            float ui0n = 0.0f;
            if (!done) {
                ui0n = s_u[pj1];
                const float4* rp = (const float4*)(C + (size_t)(pj1 - 1) * NQ + lane * 32);
#pragma unroll
                for (int q4 = 0; q4 < 8; q4++) {
                    float4 r4 = rp[q4];
                    rowbuf[q4 * 4 + 0] = r4.x; rowbuf[q4 * 4 + 1] = r4.y;
                    rowbuf[q4 * 4 + 2] = r4.z; rowbuf[q4 * 4 + 3] = r4.w;
                }
            }

            // ---- dual updates (reference order; j1 still 'unused' here) ----
            if (lane == 0) u_acc += delta;          // u[p[0]] += delta
#pragma unroll
            for (int k = 0; k < 32; k++) {
                if ((umask >> k) & 1u) {
                    v[k] -= delta;
                    int pj = s_p[jbase + k];
                    s_u[pj] += delta;               // distinct rows: race-free
                } else {
                    mv[k] -= delta;
                }
            }
            // now mark j1 used (owner lane)
            if (((j1 - 1) >> 5) == lane)
                umask |= 1u << ((j1 - 1) & 31);
            __syncwarp();                           // publish u, way

            if (done) { jfree = j1; break; }
            i0 = pj1; ui0 = ui0n; j0 = j1;
        }

        // ---- augment along way[] (lane 0) + write back free row's u ----
        if (lane == 0) {
            s_u[i] = u_acc;
            int jj = jfree;
            do {
                int jn = s_way[jj];
                s_p[jj] = s_p[jn];
                jj = jn;
            } while (jj != 0);
        }
        __syncwarp();
    }

    // ---- output: ballot compaction, ascending query ids ----
    int base = 0;
    for (int c = 0; c < 32; c++) {
        int j  = c * 32 + lane + 1;
        int pi = s_p[j];
        bool m = pi > 0;
        unsigned bal = __ballot_sync(FULL, m);
        int pos = base + __popc(bal & ((1u << lane) - 1u));
        if (m) {
            out[b * NT + pos]           = (float)(j - 1);   // rows (query)
            out[BS * NT + b * NT + pos] = (float)(pi - 1);  // cols (target)
        }
        base += __popc(bal);
    }
}

// ---------------------------------------------------------------------------
extern "C" void kernel_launch(void* const* d_in, const int* in_sizes, int n_in,
                              void* d_out, int out_size)
{
    // Identify inputs by element count (robust to ordering).
    const float *qc = 0, *ql = 0, *tc = 0, *tl = 0;
    for (int i = 0; i < n_in; i++) {
        switch (in_sizes[i]) {
            case 32768: qc = (const float*)d_in[i]; break;
            case 16384: ql = (const float*)d_in[i]; break;
            case 4096:  tc = (const float*)d_in[i]; break;
            case 2048:  tl = (const float*)d_in[i]; break;
        }
    }

    cost_kernel<<<BS, 1024>>>(qc, ql, tc, tl);
    lsa_kernel<<<BS, 32>>>((float*)d_out);
}

// round 7
// speedup vs baseline: 9.2602x; 3.0089x over previous
#include <cuda_runtime.h>
#include <math.h>

#define BS 16
#define NQ 1024   // columns m (queries)
#define NT 128    // rows n (targets)
#define INF_F 1e9f
#define FULL 0xffffffffu

#define NWARP 8
#define THREADS (NWARP * 32)   // 256
#define CPL 4                  // columns per thread

// 16 * 128 * 1024 * 4B = 8 MB cost scratch
__device__ __align__(16) float g_cost[BS * NT * NQ];

// ---------------------------------------------------------------------------
// Kernel 1: cost matrix C[b][t][q] = 5*(|dx|+|dy|) + |sigmoid(ql)-tl|
// grid (BS, 8): block handles 16 target rows. FMA contraction suppressed.
// ---------------------------------------------------------------------------
__global__ void __launch_bounds__(1024) cost_kernel(
    const float* __restrict__ qc,   // [BS, NQ, 2]
    const float* __restrict__ ql,   // [BS, NQ, 1]
    const float* __restrict__ tc,   // [BS, NT, 2]
    const float* __restrict__ tl)   // [BS, NT, 1]
{
    int b  = blockIdx.x;
    int t0 = blockIdx.y * 16;
    int q  = threadIdx.x;

    __shared__ float s_tx[16], s_ty[16], s_tp[16];
    if (q < 16) {
        int t = t0 + q;
        s_tx[q] = tc[(b * NT + t) * 2 + 0];
        s_ty[q] = tc[(b * NT + t) * 2 + 1];
        s_tp[q] = tl[b * NT + t];
    }

    float x = qc[(b * NQ + q) * 2 + 0];
    float y = qc[(b * NQ + q) * 2 + 1];
    float s = 1.0f / (1.0f + expf(-ql[b * NQ + q]));

    __syncthreads();

    float* Cb = g_cost + (size_t)b * NT * NQ;
#pragma unroll
    for (int tt = 0; tt < 16; tt++) {
        float dsum = __fadd_rn(fabsf(__fadd_rn(x, -s_tx[tt])),
                               fabsf(__fadd_rn(y, -s_ty[tt])));
        float c = __fadd_rn(__fmul_rn(5.0f, dsum),
                            fabsf(__fadd_rn(s, -s_tp[tt])));
        Cb[(t0 + tt) * NQ + q] = c;
    }
}

// ---------------------------------------------------------------------------
// Kernel 2: Jonker-Volgenant LSA, 8 warps (256 threads) per batch.
// Thread t owns columns j-1 in [t*4, t*4+4). v/minv/u-accumulators in
// registers; one __syncthreads per Dijkstra step (double-buffered partials).
// Exact reference float op sequence -> bit-identical assignment.
// ---------------------------------------------------------------------------
__global__ void __launch_bounds__(THREADS) lsa_kernel(float* __restrict__ out)
{
    const int b    = blockIdx.x;
    const int tid  = threadIdx.x;
    const int lane = tid & 31;
    const int wid  = tid >> 5;
    const float* C = g_cost + (size_t)b * NT * NQ;

    __shared__ float s_u[NT + 1];
    __shared__ int   s_p[NQ + 1];
    __shared__ int   s_way[NQ + 1];
    __shared__ unsigned long long s_part[2][NWARP];

    float v[CPL], mv[CPL], rowbuf[CPL], u_local[CPL];
    int   pj_reg[CPL];

#pragma unroll
    for (int k = 0; k < CPL; k++) v[k] = 0.0f;
    for (int j = tid; j <= NQ; j += THREADS) s_p[j] = 0;
    for (int r = tid; r <= NT; r += THREADS) s_u[r] = 0.0f;
    __syncthreads();

    const int jbase = tid * CPL + 1;   // first owned column (1-based)

    for (int i = 1; i <= NT; i++) {
#pragma unroll
        for (int k = 0; k < CPL; k++) mv[k] = INF_F;
        unsigned umask = 0u;
        float ui0   = 0.0f;            // u of fresh row i is 0
        float u_acc = 0.0f;            // thread 0: accumulates u[p[0]]
        if (tid == 0) s_p[0] = i;

        // fetch first row (i)
        {
            float4 r4 = *(const float4*)(C + (size_t)(i - 1) * NQ + tid * CPL);
            rowbuf[0] = r4.x; rowbuf[1] = r4.y; rowbuf[2] = r4.z; rowbuf[3] = r4.w;
        }

        int j0 = 0, jfree = 0, step = 0;
        for (;;) {
            // ---- relax own columns (registers) ----
#pragma unroll
            for (int k = 0; k < CPL; k++) {
                if (!((umask >> k) & 1u)) {
                    float cur = rowbuf[k] - ui0 - v[k];
                    if (cur < mv[k]) { mv[k] = cur; s_way[jbase + k] = j0; }
                }
            }

            // ---- local argmin (lowest idx wins ties) ----
            float tv0 = ((umask >> 0) & 1u) ? INF_F : mv[0];
            float tv1 = ((umask >> 1) & 1u) ? INF_F : mv[1];
            float tv2 = ((umask >> 2) & 1u) ? INF_F : mv[2];
            float tv3 = ((umask >> 3) & 1u) ? INF_F : mv[3];
            int ti0 = jbase, ti1 = jbase + 1, ti2 = jbase + 2, ti3 = jbase + 3;
            if (tv1 < tv0) { tv0 = tv1; ti0 = ti1; }
            if (tv3 < tv2) { tv2 = tv3; ti2 = ti3; }
            if (tv2 < tv0) { tv0 = tv2; ti0 = ti2; }

            // ---- warp argmin via redux (lexicographic: val, then j) ----
            float cv = tv0 + 0.0f;                    // canonicalize -0 -> +0
            unsigned ub  = __float_as_uint(cv);
            unsigned key = (ub & 0x80000000u) ? ~ub : (ub | 0x80000000u);
            unsigned mk  = __reduce_min_sync(FULL, key);
            unsigned ci  = (key == mk) ? (unsigned)ti0 : 0xffffffffu;
            unsigned jw  = __reduce_min_sync(FULL, ci);
            if (lane == 0)
                s_part[step & 1][wid] = ((unsigned long long)mk << 32) | jw;
            __syncthreads();

            // ---- every thread combines the 8 partials identically ----
            unsigned long long best = s_part[step & 1][0];
#pragma unroll
            for (int w = 1; w < NWARP; w++) {
                unsigned long long p64 = s_part[step & 1][w];
                if (p64 < best) best = p64;
            }
            const int j1 = (int)(unsigned)best;
            unsigned gk  = (unsigned)(best >> 32);
            unsigned du  = (gk & 0x80000000u) ? (gk ^ 0x80000000u) : ~gk;
            const float delta = __uint_as_float(du);

            // ---- next-row info + fetch (u[i0n] untouched this Dijkstra) ----
            const int  i0n  = s_p[j1];
            const bool done = (i0n == 0);
            float ui0n = 0.0f;
            if (!done) {
                ui0n = s_u[i0n];
                float4 r4 = *(const float4*)(C + (size_t)(i0n - 1) * NQ + tid * CPL);
                rowbuf[0] = r4.x; rowbuf[1] = r4.y; rowbuf[2] = r4.z; rowbuf[3] = r4.w;
            }

            // ---- dual updates (pure registers; reference order) ----
            if (tid == 0) u_acc += delta;             // u[p[0]] += delta
#pragma unroll
            for (int k = 0; k < CPL; k++) {
                if ((umask >> k) & 1u) {
                    v[k]       -= delta;
                    u_local[k] += delta;              // u[p[jbase+k]]
                } else {
                    mv[k] -= delta;
                }
            }

            if (done) { jfree = j1; break; }

            // mark j1 used on its owner thread; seed its u register
            if ((j1 - 1) / CPL == tid) {
                int kk = (j1 - 1) & (CPL - 1);
#pragma unroll
                for (int k = 0; k < CPL; k++) {
                    if (k == kk) {
                        umask |= 1u << k;
                        pj_reg[k]  = i0n;
                        u_local[k] = ui0n;
                    }
                }
            }
            ui0 = ui0n; j0 = j1; step++;
        }

        // ---- flush u accumulators (distinct rows: race-free) ----
#pragma unroll
        for (int k = 0; k < CPL; k++)
            if ((umask >> k) & 1u) s_u[pj_reg[k]] = u_local[k];
        if (tid == 0) s_u[i] = u_acc;

        // ---- augment along way[] (thread 0) ----
        if (tid == 0) {
            int jj = jfree;
            do {
                int jn = s_way[jj];
                s_p[jj] = s_p[jn];
                jj = jn;
            } while (jj != 0);
        }
        __syncthreads();   // publish u, p for next row
    }

    // ---- output (warp 0): ballot compaction, ascending query ids ----
    if (wid == 0) {
        int base = 0;
        for (int c = 0; c < 32; c++) {
            int j  = c * 32 + lane + 1;
            int pi = s_p[j];
            bool m = pi > 0;
            unsigned bal = __ballot_sync(FULL, m);
            int pos = base + __popc(bal & ((1u << lane) - 1u));
            if (m) {
                out[b * NT + pos]           = (float)(j - 1);   // rows (query)
                out[BS * NT + b * NT + pos] = (float)(pi - 1);  // cols (target)
            }
            base += __popc(bal);
        }
    }
}

// ---------------------------------------------------------------------------
extern "C" void kernel_launch(void* const* d_in, const int* in_sizes, int n_in,
                              void* d_out, int out_size)
{
    // Identify inputs by element count (robust to ordering).
    const float *qc = 0, *ql = 0, *tc = 0, *tl = 0;
    for (int i = 0; i < n_in; i++) {
        switch (in_sizes[i]) {
            case 32768: qc = (const float*)d_in[i]; break;
            case 16384: ql = (const float*)d_in[i]; break;
            case 4096:  tc = (const float*)d_in[i]; break;
            case 2048:  tl = (const float*)d_in[i]; break;
        }
    }

    cost_kernel<<<dim3(BS, 8), 1024>>>(qc, ql, tc, tl);
    lsa_kernel<<<BS, THREADS>>>((float*)d_out);
}

// round 8
// speedup vs baseline: 10.8049x; 1.1668x over previous
#include <cuda_runtime.h>
#include <math.h>

#define BS 16
#define NQ 1024   // columns m (queries)
#define NT 128    // rows n (targets)
#define INF_F 1e9f
#define FULL 0xffffffffu

#define NWARP 8
#define THREADS (NWARP * 32)   // 256
#define CPL 4                  // columns per thread

#define NROWS_S 52                        // rows cached in shared (208 KB)
#define ROWS_SMEM_BYTES (NROWS_S * NQ * 4)

// 16 * 128 * 1024 * 4B = 8 MB cost scratch
__device__ __align__(16) float g_cost[BS * NT * NQ];

// ---------------------------------------------------------------------------
// Kernel 1: cost matrix C[b][t][q] = 5*(|dx|+|dy|) + |sigmoid(ql)-tl|
// grid (BS, 8): block handles 16 target rows. FMA contraction suppressed.
// ---------------------------------------------------------------------------
__global__ void __launch_bounds__(1024) cost_kernel(
    const float* __restrict__ qc,   // [BS, NQ, 2]
    const float* __restrict__ ql,   // [BS, NQ, 1]
    const float* __restrict__ tc,   // [BS, NT, 2]
    const float* __restrict__ tl)   // [BS, NT, 1]
{
    int b  = blockIdx.x;
    int t0 = blockIdx.y * 16;
    int q  = threadIdx.x;

    __shared__ float s_tx[16], s_ty[16], s_tp[16];
    if (q < 16) {
        int t = t0 + q;
        s_tx[q] = tc[(b * NT + t) * 2 + 0];
        s_ty[q] = tc[(b * NT + t) * 2 + 1];
        s_tp[q] = tl[b * NT + t];
    }

    float x = qc[(b * NQ + q) * 2 + 0];
    float y = qc[(b * NQ + q) * 2 + 1];
    float s = 1.0f / (1.0f + expf(-ql[b * NQ + q]));

    __syncthreads();

    float* Cb = g_cost + (size_t)b * NT * NQ;
#pragma unroll
    for (int tt = 0; tt < 16; tt++) {
        float dsum = __fadd_rn(fabsf(__fadd_rn(x, -s_tx[tt])),
                               fabsf(__fadd_rn(y, -s_ty[tt])));
        float c = __fadd_rn(__fmul_rn(5.0f, dsum),
                            fabsf(__fadd_rn(s, -s_tp[tt])));
        Cb[(t0 + tt) * NQ + q] = c;
    }
}

// ---------------------------------------------------------------------------
// Kernel 2: Jonker-Volgenant LSA, 8 warps (256 threads) per batch.
// Thread t owns columns j-1 in [t*4, t*4+4). v/minv/u-accumulators in
// registers; one __syncthreads per Dijkstra step. First NROWS_S cost rows
// cached in dynamic shared memory (hottest rows: tree rows are uniform over
// assigned rows, so low indices are revisited most).
// Exact reference float op sequence -> bit-identical assignment.
// ---------------------------------------------------------------------------
__global__ void __launch_bounds__(THREADS) lsa_kernel(float* __restrict__ out)
{
    const int b    = blockIdx.x;
    const int tid  = threadIdx.x;
    const int lane = tid & 31;
    const int wid  = tid >> 5;
    const float* C = g_cost + (size_t)b * NT * NQ;

    extern __shared__ float s_rows[];        // [NROWS_S][NQ]

    __shared__ float s_u[NT + 1];
    __shared__ int   s_p[NQ + 1];
    __shared__ int   s_way[NQ + 1];
    __shared__ unsigned long long s_part[2][NWARP];

    float v[CPL], mv[CPL], rowbuf[CPL], u_local[CPL];
    int   pj_reg[CPL];

    // fill row cache (coalesced float4 copy)
    {
        const float4* src = (const float4*)C;
        float4*       dst = (float4*)s_rows;
#pragma unroll 4
        for (int idx = tid; idx < NROWS_S * (NQ / 4); idx += THREADS)
            dst[idx] = src[idx];
    }

#pragma unroll
    for (int k = 0; k < CPL; k++) v[k] = 0.0f;
    for (int j = tid; j <= NQ; j += THREADS) s_p[j] = 0;
    for (int r = tid; r <= NT; r += THREADS) s_u[r] = 0.0f;
    __syncthreads();

    const int jbase = tid * CPL + 1;   // first owned column (1-based)
    const int coff  = tid * CPL;       // float offset within a row

    for (int i = 1; i <= NT; i++) {
#pragma unroll
        for (int k = 0; k < CPL; k++) mv[k] = INF_F;
        unsigned umask = 0u;
        float ui0   = 0.0f;            // u of fresh row i is 0
        float u_acc = 0.0f;            // thread 0: accumulates u[p[0]]
        if (tid == 0) s_p[0] = i;

        // fetch first row (i): shared if cached, else global
        {
            float4 r4;
            if (i <= NROWS_S)
                r4 = *(const float4*)(s_rows + (size_t)(i - 1) * NQ + coff);
            else
                r4 = *(const float4*)(C + (size_t)(i - 1) * NQ + coff);
            rowbuf[0] = r4.x; rowbuf[1] = r4.y; rowbuf[2] = r4.z; rowbuf[3] = r4.w;
        }

        int j0 = 0, jfree = 0, step = 0;
        for (;;) {
            // ---- relax own columns (registers) ----
#pragma unroll
            for (int k = 0; k < CPL; k++) {
                if (!((umask >> k) & 1u)) {
                    float cur = rowbuf[k] - ui0 - v[k];
                    if (cur < mv[k]) { mv[k] = cur; s_way[jbase + k] = j0; }
                }
            }

            // ---- local argmin (lowest idx wins ties) ----
            float tv0 = ((umask >> 0) & 1u) ? INF_F : mv[0];
            float tv1 = ((umask >> 1) & 1u) ? INF_F : mv[1];
            float tv2 = ((umask >> 2) & 1u) ? INF_F : mv[2];
            float tv3 = ((umask >> 3) & 1u) ? INF_F : mv[3];
            int ti0 = jbase, ti2 = jbase + 2;
            if (tv1 < tv0) { tv0 = tv1; ti0 = jbase + 1; }
            if (tv3 < tv2) { tv2 = tv3; ti2 = jbase + 3; }
            if (tv2 < tv0) { tv0 = tv2; ti0 = ti2; }

            // ---- warp argmin via redux (lexicographic: val, then j) ----
            float cv = tv0 + 0.0f;                    // canonicalize -0 -> +0
            unsigned ub  = __float_as_uint(cv);
            unsigned key = (ub & 0x80000000u) ? ~ub : (ub | 0x80000000u);
            unsigned mk  = __reduce_min_sync(FULL, key);
            unsigned ci  = (key == mk) ? (unsigned)ti0 : 0xffffffffu;
            unsigned jw  = __reduce_min_sync(FULL, ci);
            if (lane == 0)
                s_part[step & 1][wid] = ((unsigned long long)mk << 32) | jw;
            __syncthreads();

            // ---- every thread combines the 8 partials identically ----
            unsigned long long best = s_part[step & 1][0];
#pragma unroll
            for (int w = 1; w < NWARP; w++) {
                unsigned long long p64 = s_part[step & 1][w];
                if (p64 < best) best = p64;
            }
            const int j1 = (int)(unsigned)best;
            unsigned gk  = (unsigned)(best >> 32);
            unsigned du  = (gk & 0x80000000u) ? (gk ^ 0x80000000u) : ~gk;
            const float delta = __uint_as_float(du);

            // ---- next-row info + fetch (u[i0n] untouched this Dijkstra) ----
            const int  i0n  = s_p[j1];
            const bool done = (i0n == 0);
            float ui0n = 0.0f;
            if (!done) {
                ui0n = s_u[i0n];
                float4 r4;
                if (i0n <= NROWS_S)
                    r4 = *(const float4*)(s_rows + (size_t)(i0n - 1) * NQ + coff);
                else
                    r4 = *(const float4*)(C + (size_t)(i0n - 1) * NQ + coff);
                rowbuf[0] = r4.x; rowbuf[1] = r4.y; rowbuf[2] = r4.z; rowbuf[3] = r4.w;
            }

            // ---- dual updates (pure registers; reference order) ----
            if (tid == 0) u_acc += delta;             // u[p[0]] += delta
#pragma unroll
            for (int k = 0; k < CPL; k++) {
                if ((umask >> k) & 1u) {
                    v[k]       -= delta;
                    u_local[k] += delta;              // u[p[jbase+k]]
                } else {
                    mv[k] -= delta;
                }
            }

            if (done) { jfree = j1; break; }

            // mark j1 used on its owner thread; seed its u register
            if ((j1 - 1) / CPL == tid) {
                int kk = (j1 - 1) & (CPL - 1);
#pragma unroll
                for (int k = 0; k < CPL; k++) {
                    if (k == kk) {
                        umask |= 1u << k;
                        pj_reg[k]  = i0n;
                        u_local[k] = ui0n;
                    }
                }
            }
            ui0 = ui0n; j0 = j1; step++;
        }

        // ---- flush u accumulators (distinct rows: race-free) ----
#pragma unroll
        for (int k = 0; k < CPL; k++)
            if ((umask >> k) & 1u) s_u[pj_reg[k]] = u_local[k];
        if (tid == 0) s_u[i] = u_acc;

        // ---- augment along way[] (thread 0) ----
        if (tid == 0) {
            int jj = jfree;
            do {
                int jn = s_way[jj];
                s_p[jj] = s_p[jn];
                jj = jn;
            } while (jj != 0);
        }
        __syncthreads();   // publish u, p for next row
    }

    // ---- output (warp 0): ballot compaction, ascending query ids ----
    if (wid == 0) {
        int base = 0;
        for (int c = 0; c < 32; c++) {
            int j  = c * 32 + lane + 1;
            int pi = s_p[j];
            bool m = pi > 0;
            unsigned bal = __ballot_sync(FULL, m);
            int pos = base + __popc(bal & ((1u << lane) - 1u));
            if (m) {
                out[b * NT + pos]           = (float)(j - 1);   // rows (query)
                out[BS * NT + b * NT + pos] = (float)(pi - 1);  // cols (target)
            }
            base += __popc(bal);
        }
    }
}

// ---------------------------------------------------------------------------
extern "C" void kernel_launch(void* const* d_in, const int* in_sizes, int n_in,
                              void* d_out, int out_size)
{
    // Identify inputs by element count (robust to ordering).
    const float *qc = 0, *ql = 0, *tc = 0, *tl = 0;
    for (int i = 0; i < n_in; i++) {
        switch (in_sizes[i]) {
            case 32768: qc = (const float*)d_in[i]; break;
            case 16384: ql = (const float*)d_in[i]; break;
            case 4096:  tc = (const float*)d_in[i]; break;
            case 2048:  tl = (const float*)d_in[i]; break;
        }
    }

    static int smem_set = 0;
    if (!smem_set) {
        cudaFuncSetAttribute(lsa_kernel,
                             cudaFuncAttributeMaxDynamicSharedMemorySize,
                             ROWS_SMEM_BYTES);
        smem_set = 1;
    }

    cost_kernel<<<dim3(BS, 8), 1024>>>(qc, ql, tc, tl);
    lsa_kernel<<<BS, THREADS, ROWS_SMEM_BYTES>>>((float*)d_out);
}

// round 9
// speedup vs baseline: 11.5003x; 1.0644x over previous
#include <cuda_runtime.h>
#include <math.h>

#define BS 16
#define NQ 1024   // columns m (queries)
#define NT 128    // rows n (targets)
#define INF_F 1e9f
#define FULL 0xffffffffu

#define NOWN 256               // column-owner threads (8 warps)
#define NWARP 8                // owner warps
#define THREADS 288            // + 1 orchestrator warp
#define CPL 4                  // columns per owner thread

#define NROWS_S 53             // rows cached in shared (212 KB)
#define ROWS_SMEM_BYTES (NROWS_S * NQ * 4)

// 16 * 128 * 1024 * 4B = 8 MB cost scratch
__device__ __align__(16) float g_cost[BS * NT * NQ];

// ---------------------------------------------------------------------------
// Kernel 1: cost matrix C[b][t][q] = 5*(|dx|+|dy|) + |sigmoid(ql)-tl|
// ---------------------------------------------------------------------------
__global__ void __launch_bounds__(1024) cost_kernel(
    const float* __restrict__ qc,   // [BS, NQ, 2]
    const float* __restrict__ ql,   // [BS, NQ, 1]
    const float* __restrict__ tc,   // [BS, NT, 2]
    const float* __restrict__ tl)   // [BS, NT, 1]
{
    int b  = blockIdx.x;
    int t0 = blockIdx.y * 16;
    int q  = threadIdx.x;

    __shared__ float s_tx[16], s_ty[16], s_tp[16];
    if (q < 16) {
        int t = t0 + q;
        s_tx[q] = tc[(b * NT + t) * 2 + 0];
        s_ty[q] = tc[(b * NT + t) * 2 + 1];
        s_tp[q] = tl[b * NT + t];
    }

    float x = qc[(b * NQ + q) * 2 + 0];
    float y = qc[(b * NQ + q) * 2 + 1];
    float s = 1.0f / (1.0f + expf(-ql[b * NQ + q]));

    __syncthreads();

    float* Cb = g_cost + (size_t)b * NT * NQ;
#pragma unroll
    for (int tt = 0; tt < 16; tt++) {
        float dsum = __fadd_rn(fabsf(__fadd_rn(x, -s_tx[tt])),
                               fabsf(__fadd_rn(y, -s_ty[tt])));
        float c = __fadd_rn(__fmul_rn(5.0f, dsum),
                            fabsf(__fadd_rn(s, -s_tp[tt])));
        Cb[(t0 + tt) * NQ + q] = c;
    }
}

// ---------------------------------------------------------------------------
// Kernel 2: JV LSA, 288 threads/batch. Owners (tid<256) hold 4 columns each
// (v/minv/u in registers). Warp 8 orchestrates: the augment walk for row i
// overlaps the owners' first relax of row i+1 (way[] epoch-tagged so the
// fresh relax writes no way entries). Exactly one __syncthreads per step.
// Exact reference float op sequence -> bit-identical assignment.
// ---------------------------------------------------------------------------
__global__ void __launch_bounds__(THREADS) lsa_kernel(float* __restrict__ out)
{
    const int b    = blockIdx.x;
    const int tid  = threadIdx.x;
    const int lane = tid & 31;
    const int wid  = tid >> 5;
    const bool owner = (tid < NOWN);
    const float* C = g_cost + (size_t)b * NT * NQ;

    extern __shared__ float s_rows[];        // [NROWS_S][NQ]

    __shared__ float    s_u[NT + 1];
    __shared__ int      s_p[NQ + 1];
    __shared__ unsigned s_way[NQ + 1];       // (epoch<<12) | j0
    __shared__ unsigned long long s_part[2][NWARP];

    // fill row cache (coalesced float4 copy)
    {
        const float4* src = (const float4*)C;
        float4*       dst = (float4*)s_rows;
#pragma unroll 4
        for (int idx = tid; idx < NROWS_S * (NQ / 4); idx += THREADS)
            dst[idx] = src[idx];
    }
    for (int j = tid; j <= NQ; j += THREADS) { s_p[j] = 0; s_way[j] = 0u; }
    for (int r = tid; r <= NT; r += THREADS) s_u[r] = 0.0f;
    if (tid == 0) s_p[0] = 1;

    const int jbase = tid * CPL + 1;
    const int coff  = tid * CPL;

    float v[CPL], mv[CPL], rowbuf[CPL], u_local[CPL];
    int   pj_reg[CPL];

#pragma unroll
    for (int k = 0; k < CPL; k++) { v[k] = 0.0f; mv[k] = INF_F; }

    __syncthreads();

    // owners fetch row 1 (always cached)
    if (owner) {
        float4 r4 = *(const float4*)(s_rows + coff);
        rowbuf[0] = r4.x; rowbuf[1] = r4.y; rowbuf[2] = r4.z; rowbuf[3] = r4.w;
    }

    int      i     = 1;
    int      j0    = 0;        // 0 => fresh relax (no way writes)
    unsigned umask = 0u;
    float    ui0   = 0.0f;
    float    u_acc = 0.0f;     // warp 8: u[p[0]] accumulator
    int      gs    = 0;

    for (;;) {
        if (owner) {
            // ---- relax ----
            if (j0 == 0) {
#pragma unroll
                for (int k = 0; k < CPL; k++) {
                    float cur = rowbuf[k] - v[k];           // ui0 == 0
                    if (cur < mv[k]) mv[k] = cur;           // way = 0 implicit
                }
            } else {
                unsigned wtag = ((unsigned)i << 12) | (unsigned)j0;
#pragma unroll
                for (int k = 0; k < CPL; k++) {
                    if (!((umask >> k) & 1u)) {
                        float cur = rowbuf[k] - ui0 - v[k];
                        if (cur < mv[k]) { mv[k] = cur; s_way[jbase + k] = wtag; }
                    }
                }
            }

            // ---- local argmin (lowest idx wins ties) ----
            float tv0 = ((umask >> 0) & 1u) ? INF_F : mv[0];
            float tv1 = ((umask >> 1) & 1u) ? INF_F : mv[1];
            float tv2 = ((umask >> 2) & 1u) ? INF_F : mv[2];
            float tv3 = ((umask >> 3) & 1u) ? INF_F : mv[3];
            int ti0 = jbase, ti2 = jbase + 2;
            if (tv1 < tv0) { tv0 = tv1; ti0 = jbase + 1; }
            if (tv3 < tv2) { tv2 = tv3; ti2 = jbase + 3; }
            if (tv2 < tv0) { tv0 = tv2; ti0 = ti2; }

            // ---- warp argmin via redux (lexicographic) ----
            float cv = tv0 + 0.0f;                          // -0 -> +0
            unsigned ub  = __float_as_uint(cv);
            unsigned key = (ub & 0x80000000u) ? ~ub : (ub | 0x80000000u);
            unsigned mk  = __reduce_min_sync(FULL, key);
            unsigned ci  = (key == mk) ? (unsigned)ti0 : 0xffffffffu;
            unsigned jw  = __reduce_min_sync(FULL, ci);
            if (lane == 0)
                s_part[gs & 1][wid] = ((unsigned long long)mk << 32) | jw;
        }
        __syncthreads();

        // ---- combine partials (all threads identically) ----
        unsigned long long best = s_part[gs & 1][0];
#pragma unroll
        for (int w = 1; w < NWARP; w++) {
            unsigned long long p64 = s_part[gs & 1][w];
            if (p64 < best) best = p64;
        }
        gs++;
        const int j1 = (int)(unsigned)best;
        unsigned gk  = (unsigned)(best >> 32);
        unsigned du  = (gk & 0x80000000u) ? (gk ^ 0x80000000u) : ~gk;
        const float delta = __uint_as_float(du);

        const int  i0n  = s_p[j1];
        const bool done = (i0n == 0);

        if (owner) {
            float ui0n = 0.0f;
            float nb0, nb1, nb2, nb3;
            if (!done) {
                ui0n = s_u[i0n];
                float4 r4;
                if (i0n <= NROWS_S)
                    r4 = *(const float4*)(s_rows + (size_t)(i0n - 1) * NQ + coff);
                else
                    r4 = *(const float4*)(C + (size_t)(i0n - 1) * NQ + coff);
                nb0 = r4.x; nb1 = r4.y; nb2 = r4.z; nb3 = r4.w;
            }

            // ---- dual updates (j1 still 'unused' here; reference order) ----
#pragma unroll
            for (int k = 0; k < CPL; k++) {
                if ((umask >> k) & 1u) {
                    v[k]       -= delta;
                    u_local[k] += delta;
                } else {
                    mv[k] -= delta;
                }
            }

            if (!done) {
                if ((j1 - 1) / CPL == tid) {
                    int kk = (j1 - 1) & (CPL - 1);
#pragma unroll
                    for (int k = 0; k < CPL; k++) {
                        if (k == kk) {
                            umask |= 1u << k;
                            pj_reg[k]  = i0n;
                            u_local[k] = ui0n;
                        }
                    }
                }
                ui0 = ui0n; j0 = j1;
                rowbuf[0] = nb0; rowbuf[1] = nb1;
                rowbuf[2] = nb2; rowbuf[3] = nb3;
            } else {
                // flush u of my used columns (distinct rows: race-free)
#pragma unroll
                for (int k = 0; k < CPL; k++)
                    if ((umask >> k) & 1u) s_u[pj_reg[k]] = u_local[k];
                if (i == NT) break;
                // start next row: fetch + reset (augment overlaps in warp 8)
                i++;
#pragma unroll
                for (int k = 0; k < CPL; k++) mv[k] = INF_F;
                umask = 0u; ui0 = 0.0f; j0 = 0;
                float4 r4;
                if (i <= NROWS_S)
                    r4 = *(const float4*)(s_rows + (size_t)(i - 1) * NQ + coff);
                else
                    r4 = *(const float4*)(C + (size_t)(i - 1) * NQ + coff);
                rowbuf[0] = r4.x; rowbuf[1] = r4.y;
                rowbuf[2] = r4.z; rowbuf[3] = r4.w;
            }
        } else {
            u_acc += delta;                       // u[p[0]] accumulation
            if (done) {
                if (tid == NOWN) {
                    s_u[i] = u_acc;
                    // augment along epoch-tagged way[] (reads epoch == i;
                    // owners' fresh relax writes no way entries -> race-free)
                    int jj = j1;
                    do {
                        unsigned w  = s_way[jj];
                        int      jn = ((w >> 12) == (unsigned)i)
                                      ? (int)(w & 0xFFFu) : 0;
                        s_p[jj] = s_p[jn];
                        jj = jn;
                    } while (jj != 0);
                }
                if (i == NT) break;
                i++;
                u_acc = 0.0f;
                if (tid == NOWN) s_p[0] = i;      // for next Dijkstra
            }
        }
    }
    __syncthreads();   // final augment visible

    // ---- output (warp 0): ballot compaction, ascending query ids ----
    if (wid == 0) {
        int base = 0;
        for (int c = 0; c < 32; c++) {
            int j  = c * 32 + lane + 1;
            int pi = s_p[j];
            bool m = pi > 0;
            unsigned bal = __ballot_sync(FULL, m);
            int pos = base + __popc(bal & ((1u << lane) - 1u));
            if (m) {
                out[b * NT + pos]           = (float)(j - 1);   // rows (query)
                out[BS * NT + b * NT + pos] = (float)(pi - 1);  // cols (target)
            }
            base += __popc(bal);
        }
    }
}

// ---------------------------------------------------------------------------
extern "C" void kernel_launch(void* const* d_in, const int* in_sizes, int n_in,
                              void* d_out, int out_size)
{
    // Identify inputs by element count (robust to ordering).
    const float *qc = 0, *ql = 0, *tc = 0, *tl = 0;
    for (int i = 0; i < n_in; i++) {
        switch (in_sizes[i]) {
            case 32768: qc = (const float*)d_in[i]; break;
            case 16384: ql = (const float*)d_in[i]; break;
            case 4096:  tc = (const float*)d_in[i]; break;
            case 2048:  tl = (const float*)d_in[i]; break;
        }
    }

    static int smem_set = 0;
    if (!smem_set) {
        cudaFuncSetAttribute(lsa_kernel,
                             cudaFuncAttributeMaxDynamicSharedMemorySize,
                             ROWS_SMEM_BYTES);
        smem_set = 1;
    }

    cost_kernel<<<dim3(BS, 8), 1024>>>(qc, ql, tc, tl);
    lsa_kernel<<<BS, THREADS, ROWS_SMEM_BYTES>>>((float*)d_out);
}

// round 13
// speedup vs baseline: 13.8740x; 1.2064x over previous
#include <cuda_runtime.h>
#include <math.h>

#define BS 16
#define NQ 1024   // columns m (queries)
#define NT 128    // rows n (targets)
#define INF_F 1e9f
#define FULL 0xffffffffu

#define NOWN 256               // column-owner threads (8 warps)
#define NWARP 8                // owner warps
#define THREADS 288            // + 1 orchestrator warp
#define CPL 4                  // columns per owner thread

// ---------------------------------------------------------------------------
// Single fused kernel: faithful Jonker-Volgenant replay (exact reference
// trajectory, zero-initialized duals) with costs recomputed on the fly
// (bit-identical to the stored-matrix expression). 288 threads per batch:
// owners (tid<256) hold 4 columns each with v/minv/u in registers; warp 8
// orchestrates (u[p[0]] accumulation + augment overlapping the owners' next
// fresh relax). Exactly one __syncthreads per Dijkstra step.
// ---------------------------------------------------------------------------
__global__ void __launch_bounds__(THREADS) hm_kernel(
    const float* __restrict__ qc,   // [BS, NQ, 2]
    const float* __restrict__ ql,   // [BS, NQ, 1]
    const float* __restrict__ tc,   // [BS, NT, 2]
    const float* __restrict__ tl,   // [BS, NT, 1]
    float* __restrict__ out)
{
    const int b    = blockIdx.x;
    const int tid  = threadIdx.x;
    const int lane = tid & 31;
    const int wid  = tid >> 5;
    const bool owner = (tid < NOWN);

    __shared__ float s_tx[NT + 1], s_ty[NT + 1], s_tp[NT + 1];
    __shared__ float    s_u[NT + 1];
    __shared__ int      s_p[NQ + 1];
    __shared__ unsigned s_way[NQ + 1];       // (row-epoch << 12) | j0
    __shared__ unsigned long long s_part[2][NWARP];

    if (tid < NT) {
        s_tx[tid + 1] = tc[(b * NT + tid) * 2 + 0];
        s_ty[tid + 1] = tc[(b * NT + tid) * 2 + 1];
        s_tp[tid + 1] = tl[b * NT + tid];
    }
    for (int j = tid; j <= NQ; j += THREADS) { s_p[j] = 0; s_way[j] = 0u; }
    for (int r = tid; r <= NT; r += THREADS) s_u[r] = 0.0f;
    if (tid == 0) s_p[0] = 1;

    const int coff  = tid * CPL;       // first owned column (0-based)
    const int jbase = coff + 1;        // first owned column (1-based)

    // per-owner query data (4 columns)
    float qx[CPL], qy[CPL], qs[CPL];
    if (owner) {
#pragma unroll
        for (int k = 0; k < CPL; k++) {
            int q = coff + k;
            qx[k] = qc[(b * NQ + q) * 2 + 0];
            qy[k] = qc[(b * NQ + q) * 2 + 1];
            qs[k] = 1.0f / (1.0f + expf(-ql[b * NQ + q]));
        }
    }

    // cost(row ii, owned col k): identical float op sequence everywhere
#define COSTK(ii, k)                                                      \
    __fadd_rn(__fmul_rn(5.0f,                                             \
        __fadd_rn(fabsf(__fadd_rn(qx[k], -s_tx[ii])),                     \
                  fabsf(__fadd_rn(qy[k], -s_ty[ii])))),                   \
        fabsf(__fadd_rn(qs[k], -s_tp[ii])))

    float v[CPL], mv[CPL], u_local[CPL];
    int   pj_reg[CPL];
#pragma unroll
    for (int k = 0; k < CPL; k++) { v[k] = 0.0f; mv[k] = INF_F; }

    __syncthreads();

    int      i     = 1;        // outer row (fresh free row)
    int      i0    = 1;        // current tree row to relax
    int      j0    = 0;        // 0 => fresh relax (no way writes)
    unsigned umask = 0u;
    float    ui0   = 0.0f;     // u[i0] at tree-entry (0 for fresh row)
    float    u_acc = 0.0f;     // orchestrator: u[p[0]] accumulator
    int      gs    = 0;

    for (;;) {
        if (owner) {
            // ---- relax (cost recomputed; (a-0)-v == a-v bitwise) ----
            if (j0 == 0) {
#pragma unroll
                for (int k = 0; k < CPL; k++) {
                    float cur = COSTK(i0, k) - ui0 - v[k];
                    if (cur < mv[k]) mv[k] = cur;           // way = 0 implicit
                }
            } else {
                unsigned wtag = ((unsigned)i << 12) | (unsigned)j0;
#pragma unroll
                for (int k = 0; k < CPL; k++) {
                    if (!((umask >> k) & 1u)) {
                        float cur = COSTK(i0, k) - ui0 - v[k];
                        if (cur < mv[k]) { mv[k] = cur; s_way[jbase + k] = wtag; }
                    }
                }
            }

            // ---- local argmin (lowest idx wins ties) ----
            float tv0 = ((umask >> 0) & 1u) ? INF_F : mv[0];
            float tv1 = ((umask >> 1) & 1u) ? INF_F : mv[1];
            float tv2 = ((umask >> 2) & 1u) ? INF_F : mv[2];
            float tv3 = ((umask >> 3) & 1u) ? INF_F : mv[3];
            int ti0 = jbase, ti2 = jbase + 2;
            if (tv1 < tv0) { tv0 = tv1; ti0 = jbase + 1; }
            if (tv3 < tv2) { tv2 = tv3; ti2 = jbase + 3; }
            if (tv2 < tv0) { tv0 = tv2; ti0 = ti2; }

            // ---- warp argmin via redux (lexicographic: val, then j) ----
            float cv = tv0 + 0.0f;                          // -0 -> +0
            unsigned ub  = __float_as_uint(cv);
            unsigned key = (ub & 0x80000000u) ? ~ub : (ub | 0x80000000u);
            unsigned mk  = __reduce_min_sync(FULL, key);
            unsigned ci  = (key == mk) ? (unsigned)ti0 : 0xffffffffu;
            unsigned jw  = __reduce_min_sync(FULL, ci);
            if (lane == 0)
                s_part[gs & 1][wid] = ((unsigned long long)mk << 32) | jw;
        }
        __syncthreads();

        // ---- combine partials (all threads identically) ----
        unsigned long long best = s_part[gs & 1][0];
#pragma unroll
        for (int w = 1; w < NWARP; w++) {
            unsigned long long p64 = s_part[gs & 1][w];
            if (p64 < best) best = p64;
        }
        gs++;
        const int j1 = (int)(unsigned)best;
        unsigned gk  = (unsigned)(best >> 32);
        unsigned du  = (gk & 0x80000000u) ? (gk ^ 0x80000000u) : ~gk;
        const float delta = __uint_as_float(du);

        const int  i0n  = s_p[j1];
        const bool done = (i0n == 0);

        if (owner) {
            // ---- dual updates (j1 still 'unused' here; reference order) ----
#pragma unroll
            for (int k = 0; k < CPL; k++) {
                if ((umask >> k) & 1u) {
                    v[k]       -= delta;
                    u_local[k] += delta;
                } else {
                    mv[k] -= delta;
                }
            }

            if (!done) {
                // mark j1 used on its owner; seed its u register
                // (s_u[i0n] untouched during this Dijkstra: pre-entry value)
                if ((unsigned)(j1 - 1) / CPL == (unsigned)tid) {
                    int kk = (j1 - 1) & (CPL - 1);
#pragma unroll
                    for (int k = 0; k < CPL; k++) {
                        if (k == kk) {
                            umask |= 1u << k;
                            pj_reg[k]  = i0n;
                            u_local[k] = s_u[i0n];
                        }
                    }
                }
                i0  = i0n;
                ui0 = s_u[i0n];
                j0  = j1;
            } else {
                // flush u of my used columns (distinct rows: race-free)
#pragma unroll
                for (int k = 0; k < CPL; k++)
                    if ((umask >> k) & 1u) s_u[pj_reg[k]] = u_local[k];
                if (i == NT) break;
                // start next outer row (augment overlaps in warp 8)
                i++;
#pragma unroll
                for (int k = 0; k < CPL; k++) mv[k] = INF_F;
                umask = 0u; ui0 = 0.0f; j0 = 0; i0 = i;
            }
        } else {
            u_acc += delta;                       // u[p[0]] accumulation
            if (done) {
                if (tid == NOWN) {
                    s_u[i] = u_acc;
                    // augment along epoch-tagged way[] (epoch == i; owners'
                    // fresh relax writes no way entries -> race-free)
                    int jj = j1;
                    do {
                        unsigned w  = s_way[jj];
                        int      jn = ((w >> 12) == (unsigned)i)
                                      ? (int)(w & 0xFFFu) : 0;
                        s_p[jj] = s_p[jn];
                        jj = jn;
                    } while (jj != 0);
                }
                if (i == NT) break;
                i++;
                u_acc = 0.0f;
                if (tid == NOWN) s_p[0] = i;      // for next Dijkstra
            }
        }
    }
#undef COSTK
    __syncthreads();   // final augment visible

    // ---- output (warp 0): ballot compaction, ascending query ids ----
    if (wid == 0) {
        int base = 0;
        for (int c = 0; c < 32; c++) {
            int j  = c * 32 + lane + 1;
            int pi = s_p[j];
            bool m = pi > 0;
            unsigned bal = __ballot_sync(FULL, m);
            int pos = base + __popc(bal & ((1u << lane) - 1u));
            if (m) {
                out[b * NT + pos]           = (float)(j - 1);   // rows (query)
                out[BS * NT + b * NT + pos] = (float)(pi - 1);  // cols (target)
            }
            base += __popc(bal);
        }
    }
}

// ---------------------------------------------------------------------------
extern "C" void kernel_launch(void* const* d_in, const int* in_sizes, int n_in,
                              void* d_out, int out_size)
{
    // Identify inputs by element count (robust to ordering).
    const float *qc = 0, *ql = 0, *tc = 0, *tl = 0;
    for (int i = 0; i < n_in; i++) {
        switch (in_sizes[i]) {
            case 32768: qc = (const float*)d_in[i]; break;
            case 16384: ql = (const float*)d_in[i]; break;
            case 4096:  tc = (const float*)d_in[i]; break;
            case 2048:  tl = (const float*)d_in[i]; break;
        }
    }

    hm_kernel<<<BS, THREADS>>>(qc, ql, tc, tl, (float*)d_out);
}